// round 6
// baseline (speedup 1.0000x reference)
#include <cuda_runtime.h>
#include <cuda_bf16.h>
#include <cuda_fp16.h>
#include <cstdint>

// ---------------------------------------------------------------------------
// GraphSAGE: out = normalize( [x | segsum(vals * x[cols])] @ W^T + b )
// N=100000, E=1600000, IN_F=OUT_F=128, rows sorted.
//
//   K0: W split -> SW128-swizzled bf16 hi/lo images (once).
//   K1: zero neighbor scratch + convert x -> fp16 copy (for SpMM gather).
//   K2: SpMM — fp16 gather (halves L2 traffic), fp32 accumulate, float4
//       atomic flush on row change.
//   K3: HMMA bf16-split GEMM. CTA 256x128, 16 warps, warp tile 64x32
//       (smem-crossbar fix: 0.083 -> 0.061 B/MAC). W resident in smem,
//       B via ldsm.x4, fused bias + row L2-normalize.
// ---------------------------------------------------------------------------

#define NNODES   100000
#define INF      128
#define TWOK     256
#define OUTF     128

__device__ float  g_neighbor[(size_t)NNODES * INF];
__device__ __half g_xh[(size_t)NNODES * INF];
__device__ __align__(128) unsigned char g_Whi_img[65536];
__device__ __align__(128) unsigned char g_Wlo_img[65536];

// ---------------------------------------------------------------------------
// helpers
// ---------------------------------------------------------------------------
__device__ __forceinline__ uint32_t smem_u32(const void* p) {
    uint32_t a;
    asm("{ .reg .u64 t; cvta.to.shared.u64 t, %1; cvt.u32.u64 %0, t; }"
        : "=r"(a) : "l"(p));
    return a;
}
__device__ __forceinline__ uint32_t sw128(uint32_t off) {
    return off ^ ((off >> 3) & 0x70);
}
__device__ __forceinline__ void ldsm_x4(uint32_t& r0, uint32_t& r1,
                                        uint32_t& r2, uint32_t& r3, uint32_t a) {
    asm volatile("ldmatrix.sync.aligned.m8n8.x4.shared.b16 {%0,%1,%2,%3}, [%4];"
                 : "=r"(r0), "=r"(r1), "=r"(r2), "=r"(r3) : "r"(a));
}
__device__ __forceinline__ void mma_bf16(float* c, const uint32_t* a,
                                         const uint32_t* b) {
    asm volatile(
        "mma.sync.aligned.m16n8k16.row.col.f32.bf16.bf16.f32 "
        "{%0,%1,%2,%3}, {%4,%5,%6,%7}, {%8,%9}, {%0,%1,%2,%3};"
        : "+f"(c[0]), "+f"(c[1]), "+f"(c[2]), "+f"(c[3])
        : "r"(a[0]), "r"(a[1]), "r"(a[2]), "r"(a[3]), "r"(b[0]), "r"(b[1]));
}
__device__ __forceinline__ void split_store(char* hi_base, char* lo_base,
                                            uint32_t sw_off, float4 v) {
    __nv_bfloat16 h0 = __float2bfloat16_rn(v.x);
    __nv_bfloat16 h1 = __float2bfloat16_rn(v.y);
    __nv_bfloat16 h2 = __float2bfloat16_rn(v.z);
    __nv_bfloat16 h3 = __float2bfloat16_rn(v.w);
    __nv_bfloat16 l0 = __float2bfloat16_rn(v.x - __bfloat162float(h0));
    __nv_bfloat16 l1 = __float2bfloat16_rn(v.y - __bfloat162float(h1));
    __nv_bfloat16 l2 = __float2bfloat16_rn(v.z - __bfloat162float(h2));
    __nv_bfloat16 l3 = __float2bfloat16_rn(v.w - __bfloat162float(h3));
    uint32_t hA = (uint32_t)__bfloat16_as_ushort(h0) | ((uint32_t)__bfloat16_as_ushort(h1) << 16);
    uint32_t hB = (uint32_t)__bfloat16_as_ushort(h2) | ((uint32_t)__bfloat16_as_ushort(h3) << 16);
    uint32_t lA = (uint32_t)__bfloat16_as_ushort(l0) | ((uint32_t)__bfloat16_as_ushort(l1) << 16);
    uint32_t lB = (uint32_t)__bfloat16_as_ushort(l2) | ((uint32_t)__bfloat16_as_ushort(l3) << 16);
    *reinterpret_cast<uint2*>(hi_base + sw_off) = make_uint2(hA, hB);
    *reinterpret_cast<uint2*>(lo_base + sw_off) = make_uint2(lA, lB);
}
#define CP_ASYNC16(dst, src) \
    asm volatile("cp.async.cg.shared.global [%0], [%1], 16;" :: "r"(dst), "l"(src))
#define CP_COMMIT() asm volatile("cp.async.commit_group;" ::: "memory")
#define CP_WAIT0()  asm volatile("cp.async.wait_group 0;" ::: "memory")

// ---------------------------------------------------------------------------
// K0: split W into SW128-swizzled bf16 hi/lo images.
// Image: [4 k-chunks][128 rows][64 bf16] (16KB per chunk), row = output col.
// ---------------------------------------------------------------------------
__global__ void wsplit_kernel(const float* __restrict__ W) {
    int i = blockIdx.x * blockDim.x + threadIdx.x;   // 0..8191 float4s
    int row   = i >> 6;
    int kf    = i & 63;
    int chunk = kf >> 4;
    int k4    = kf & 15;
    float4 wv = *reinterpret_cast<const float4*>(W + row * TWOK + chunk * 64 + k4 * 4);
    uint32_t off = chunk * 16384 + sw128((uint32_t)(row * 128 + k4 * 8));
    split_store((char*)g_Whi_img, (char*)g_Wlo_img, off, wv);
}

// ---------------------------------------------------------------------------
// K1: zero neighbor scratch + build fp16 copy of x.
//   i < n4 (3.2M):    zero one float4 of g_neighbor
//   i < nc8 (1.6M):   convert 8 floats of x -> 8 halves
// ---------------------------------------------------------------------------
__global__ void prep_kernel(const float* __restrict__ x, int n4, int nc8) {
    int i = blockIdx.x * blockDim.x + threadIdx.x;
    if (i < n4)
        reinterpret_cast<float4*>(g_neighbor)[i] = make_float4(0.f, 0.f, 0.f, 0.f);
    if (i < nc8) {
        float4 a = reinterpret_cast<const float4*>(x)[i * 2];
        float4 b = reinterpret_cast<const float4*>(x)[i * 2 + 1];
        __half2 h0 = __floats2half2_rn(a.x, a.y);
        __half2 h1 = __floats2half2_rn(a.z, a.w);
        __half2 h2 = __floats2half2_rn(b.x, b.y);
        __half2 h3 = __floats2half2_rn(b.z, b.w);
        uint4 o;
        o.x = *reinterpret_cast<uint32_t*>(&h0);
        o.y = *reinterpret_cast<uint32_t*>(&h1);
        o.z = *reinterpret_cast<uint32_t*>(&h2);
        o.w = *reinterpret_cast<uint32_t*>(&h3);
        reinterpret_cast<uint4*>(g_xh)[i] = o;
    }
}

// ---------------------------------------------------------------------------
// K2: SpMM (fp16 gather). Warp handles 32 edges: lane l loads edge (base+l)
// coalesced, 32 shfl-broadcast steps; lane owns dims [4l, 4l+4).
// ---------------------------------------------------------------------------
__global__ void spmm_kernel(const int*   __restrict__ rows,
                            const int*   __restrict__ cols,
                            const float* __restrict__ vals,
                            int E) {
    int warp = (blockIdx.x * blockDim.x + threadIdx.x) >> 5;
    int lane = threadIdx.x & 31;
    long base = (long)warp * 32;
    if (base >= E) return;

    long e = base + lane;
    bool valid = e < E;
    long es = valid ? e : (long)E - 1;
    int   r = __ldg(rows + es);
    int   c = valid ? __ldg(cols + e) : 0;
    float v = valid ? __ldg(vals + e) : 0.f;

    const uint2* xh2 = reinterpret_cast<const uint2*>(g_xh);   // 4 halves
    float4*      nb4 = reinterpret_cast<float4*>(g_neighbor);

    int cur = __shfl_sync(0xffffffffu, r, 0);
    float4 acc = make_float4(0.f, 0.f, 0.f, 0.f);

    #pragma unroll
    for (int j = 0; j < 32; j++) {
        int   rj = __shfl_sync(0xffffffffu, r, j);
        int   cj = __shfl_sync(0xffffffffu, c, j);
        float vj = __shfl_sync(0xffffffffu, v, j);
        uint2 xv = xh2[(size_t)cj * 32 + lane];
        if (rj != cur) {                       // warp-uniform
            atomicAdd(&nb4[(size_t)cur * 32 + lane], acc);
            acc = make_float4(0.f, 0.f, 0.f, 0.f);
            cur = rj;
        }
        float2 f0 = __half22float2(*reinterpret_cast<__half2*>(&xv.x));
        float2 f1 = __half22float2(*reinterpret_cast<__half2*>(&xv.y));
        acc.x = fmaf(vj, f0.x, acc.x);
        acc.y = fmaf(vj, f0.y, acc.y);
        acc.z = fmaf(vj, f1.x, acc.z);
        acc.w = fmaf(vj, f1.y, acc.w);
    }
    atomicAdd(&nb4[(size_t)cur * 32 + lane], acc);
}

// ---------------------------------------------------------------------------
// K3: bf16-split HMMA GEMM + bias + L2 normalize.
//   512 threads = 16 warps. CTA tile 256x128, warp tile 64x32 (mi4 x ni4).
//   warp_m = wid&3 (rows *64), warp_n = wid>>2 (cols *32). K=256, 4 chunks.
//   W (hi+lo) resident in smem; A single-buffered (regs at cap).
// ---------------------------------------------------------------------------
#define SM_BIAS 0
#define SM_RSS  512                  // float[4][256] = 4KB
#define SM_WHI  8192                 // 65536
#define SM_WLO  (SM_WHI + 65536)
#define SM_A    (SM_WLO + 65536)     // hi 32KB, lo 32KB
#define SM_TOTAL (SM_A + 65536)

__global__ void __launch_bounds__(512, 1)
gemm_norm_kernel(const float* __restrict__ x,
                 const float* __restrict__ b,
                 float* __restrict__ out,
                 int N) {
    extern __shared__ char smem[];
    uint32_t sb = smem_u32(smem);
    float* bias = reinterpret_cast<float*>(smem + SM_BIAS);
    float (*rss)[256] = reinterpret_cast<float (*)[256]>(smem + SM_RSS);

    int t    = threadIdx.x;
    int wid  = t >> 5;
    int lane = t & 31;
    int warp_m = wid & 3;          // rows warp_m*64 .. +63
    int warp_n = wid >> 2;         // cols warp_n*32 .. +31
    int rowBase = blockIdx.x * 256;

    // W image -> smem (async)
    #pragma unroll
    for (int j = 0; j < 8; j++) {
        CP_ASYNC16(sb + SM_WHI + t * 16 + j * 8192, g_Whi_img + t * 16 + j * 8192);
        CP_ASYNC16(sb + SM_WLO + t * 16 + j * 8192, g_Wlo_img + t * 16 + j * 8192);
    }
    CP_COMMIT();

    if (t < OUTF) bias[t] = __ldg(b + t);

    float acc[4][4][4];
    #pragma unroll
    for (int mi = 0; mi < 4; mi++)
        #pragma unroll
        for (int ni = 0; ni < 4; ni++)
            #pragma unroll
            for (int r = 0; r < 4; r++) acc[mi][ni][r] = 0.f;

    // A staging: thread covers (row = i>>4, k4 = i&15), i = t + 512s, s<8
    int sRow = t >> 4;
    int sK4  = t & 15;

    // frag addresses
    int aRow = warp_m * 64 + (lane & 15);
    int aK8  = (lane >> 4) * 8;
    int bRowX = warp_n * 32 + (lane & 7) + ((lane >> 4) & 1) * 8;
    int bK8  = ((lane >> 3) & 1) * 8;

    bool first = true;
    #pragma unroll
    for (int c = 0; c < 4; c++) {
        const float* abase = (c < 2) ? (x + c * 64)
                                     : (g_neighbor + (c - 2) * 64);
        if (!first) __syncthreads();   // compute of prev chunk done
        first = false;

        #pragma unroll
        for (int s = 0; s < 8; s++) {
            int row = sRow + 32 * s;
            int gr  = rowBase + row;
            float4 av = (gr < N)
                ? *reinterpret_cast<const float4*>(abase + (size_t)gr * INF + sK4 * 4)
                : make_float4(0.f, 0.f, 0.f, 0.f);
            uint32_t sw = sw128((uint32_t)(row * 128 + sK4 * 8));
            split_store(smem + SM_A, smem + SM_A + 32768, sw, av);
        }
        if (c == 0) CP_WAIT0();
        __syncthreads();

        uint32_t wBase = c * 16384;
        #pragma unroll
        for (int kk = 0; kk < 64; kk += 16) {
            uint32_t ahi[4][4], alo[4][4], bhi[4][2], blo[4][2];
            #pragma unroll
            for (int mi = 0; mi < 4; mi++) {
                uint32_t off = sw128((uint32_t)((aRow + mi * 16) * 128
                                                + (kk + aK8) * 2));
                ldsm_x4(ahi[mi][0], ahi[mi][1], ahi[mi][2], ahi[mi][3],
                        sb + SM_A + off);
                ldsm_x4(alo[mi][0], alo[mi][1], alo[mi][2], alo[mi][3],
                        sb + SM_A + 32768 + off);
            }
            #pragma unroll
            for (int p = 0; p < 2; p++) {
                uint32_t off = sw128((uint32_t)((bRowX + p * 16) * 128
                                                + (kk + bK8) * 2));
                ldsm_x4(bhi[2*p][0], bhi[2*p][1], bhi[2*p+1][0], bhi[2*p+1][1],
                        sb + SM_WHI + wBase + off);
                ldsm_x4(blo[2*p][0], blo[2*p][1], blo[2*p+1][0], blo[2*p+1][1],
                        sb + SM_WLO + wBase + off);
            }
            #pragma unroll
            for (int mi = 0; mi < 4; mi++)
                #pragma unroll
                for (int ni = 0; ni < 4; ni++) {
                    mma_bf16(acc[mi][ni], ahi[mi], bhi[ni]);
                    mma_bf16(acc[mi][ni], alo[mi], bhi[ni]);
                    mma_bf16(acc[mi][ni], ahi[mi], blo[ni]);
                }
        }
    }

    // ---- epilogue: bias, row sum-of-squares, normalize, store ----
    int colBase = warp_n * 32 + 2 * (lane & 3);
    #pragma unroll
    for (int mi = 0; mi < 4; mi++)
        #pragma unroll
        for (int ni = 0; ni < 4; ni++) {
            float b0 = bias[colBase + ni * 8];
            float b1 = bias[colBase + ni * 8 + 1];
            acc[mi][ni][0] += b0;  acc[mi][ni][1] += b1;
            acc[mi][ni][2] += b0;  acc[mi][ni][3] += b1;
        }

    #pragma unroll
    for (int mi = 0; mi < 4; mi++) {
        #pragma unroll
        for (int half = 0; half < 2; half++) {
            float s = 0.f;
            #pragma unroll
            for (int ni = 0; ni < 4; ni++) {
                float c0 = acc[mi][ni][half * 2 + 0];
                float c1 = acc[mi][ni][half * 2 + 1];
                s = fmaf(c0, c0, s);
                s = fmaf(c1, c1, s);
            }
            s += __shfl_xor_sync(0xffffffffu, s, 1);
            s += __shfl_xor_sync(0xffffffffu, s, 2);
            if ((lane & 3) == 0)
                rss[warp_n][warp_m * 64 + mi * 16 + half * 8 + (lane >> 2)] = s;
        }
    }
    __syncthreads();

    float2* out2 = reinterpret_cast<float2*>(out);
    #pragma unroll
    for (int mi = 0; mi < 4; mi++) {
        #pragma unroll
        for (int half = 0; half < 2; half++) {
            int rl  = warp_m * 64 + mi * 16 + half * 8 + (lane >> 2);
            int row = rowBase + rl;
            if (row < N) {
                float ss = rss[0][rl] + rss[1][rl] + rss[2][rl] + rss[3][rl];
                float scale = 1.f / fmaxf(sqrtf(ss), 1e-12f);
                #pragma unroll
                for (int ni = 0; ni < 4; ni++) {
                    float2 o;
                    o.x = acc[mi][ni][half * 2 + 0] * scale;
                    o.y = acc[mi][ni][half * 2 + 1] * scale;
                    out2[(size_t)row * 64 + (colBase + ni * 8) / 2] = o;
                }
            }
        }
    }
}

// ---------------------------------------------------------------------------
// Launch
// ---------------------------------------------------------------------------
extern "C" void kernel_launch(void* const* d_in, const int* in_sizes, int n_in,
                              void* d_out, int out_size) {
    const float* x    = (const float*)d_in[0];
    const int*   rows = (const int*)  d_in[1];
    const int*   cols = (const int*)  d_in[2];
    const float* vals = (const float*)d_in[3];
    const float* W    = (const float*)d_in[4];
    const float* b    = (const float*)d_in[5];
    float*       out  = (float*)d_out;

    int N = in_sizes[0] / INF;
    int E = in_sizes[1];

    cudaFuncSetAttribute(gemm_norm_kernel,
                         cudaFuncAttributeMaxDynamicSharedMemorySize, SM_TOTAL);

    // K0: W split (independent of SpMM result)
    wsplit_kernel<<<32, 256>>>(W);

    // K1: zero neighbor scratch + fp16 copy of x
    int n4  = N * (INF / 4);
    int nc8 = N * (INF / 8);
    prep_kernel<<<(n4 + 255) / 256, 256>>>(x, n4, nc8);

    // K2: SpMM
    int warps  = (E + 31) / 32;
    int blocks = (warps * 32 + 255) / 256;
    spmm_kernel<<<blocks, 256>>>(rows, cols, vals, E);

    // K3: HMMA GEMM + bias + normalize
    gemm_norm_kernel<<<(N + 255) / 256, 512, SM_TOTAL>>>(x, b, out, N);
}

// round 7
// speedup vs baseline: 1.4659x; 1.4659x over previous
#include <cuda_runtime.h>
#include <cuda_bf16.h>
#include <cuda_fp16.h>
#include <cstdint>

// ---------------------------------------------------------------------------
// GraphSAGE: out = normalize( [x | segsum(vals * x[cols])] @ W^T + b )
// N=100000, E=1600000, IN_F=OUT_F=128, rows sorted.
//
//   K0: W -> fp16 SW128-swizzled image (once).
//   K1: zero neighbor scratch + x -> fp16 copy (gather source + GEMM A).
//   K2: SpMM — fp16 gather, fp32 accumulate, float4 atomic flush.
//   K3: neighbor fp32 -> fp16.
//   K4: fp16 HMMA GEMM (single product; rel_err ~3e-4 << 1e-3), pure
//       cp.async staging, 2 CTAs/SM, fused bias + row L2-normalize.
// ---------------------------------------------------------------------------

#define NNODES   100000
#define INF      128
#define TWOK     256
#define OUTF     128

__device__ float  g_neighbor[(size_t)NNODES * INF];
__device__ __half g_xh[(size_t)NNODES * INF];
__device__ __half g_nh[(size_t)NNODES * INF];
__device__ __align__(128) unsigned char g_Wh_img[65536];

// ---------------------------------------------------------------------------
// helpers
// ---------------------------------------------------------------------------
__device__ __forceinline__ uint32_t smem_u32(const void* p) {
    uint32_t a;
    asm("{ .reg .u64 t; cvta.to.shared.u64 t, %1; cvt.u32.u64 %0, t; }"
        : "=r"(a) : "l"(p));
    return a;
}
__device__ __forceinline__ uint32_t sw128(uint32_t off) {
    return off ^ ((off >> 3) & 0x70);
}
__device__ __forceinline__ void ldsm_x4(uint32_t& r0, uint32_t& r1,
                                        uint32_t& r2, uint32_t& r3, uint32_t a) {
    asm volatile("ldmatrix.sync.aligned.m8n8.x4.shared.b16 {%0,%1,%2,%3}, [%4];"
                 : "=r"(r0), "=r"(r1), "=r"(r2), "=r"(r3) : "r"(a));
}
__device__ __forceinline__ void mma_f16(float* c, const uint32_t* a,
                                        const uint32_t* b) {
    asm volatile(
        "mma.sync.aligned.m16n8k16.row.col.f32.f16.f16.f32 "
        "{%0,%1,%2,%3}, {%4,%5,%6,%7}, {%8,%9}, {%0,%1,%2,%3};"
        : "+f"(c[0]), "+f"(c[1]), "+f"(c[2]), "+f"(c[3])
        : "r"(a[0]), "r"(a[1]), "r"(a[2]), "r"(a[3]), "r"(b[0]), "r"(b[1]));
}
#define CP_ASYNC16(dst, src) \
    asm volatile("cp.async.cg.shared.global [%0], [%1], 16;" :: "r"(dst), "l"(src))
#define CP_ASYNC16Z(dst, src, sz) \
    asm volatile("cp.async.cg.shared.global [%0], [%1], 16, %2;" \
                 :: "r"(dst), "l"(src), "r"(sz))
#define CP_COMMIT() asm volatile("cp.async.commit_group;" ::: "memory")
#define CP_WAIT1()  asm volatile("cp.async.wait_group 1;" ::: "memory")
#define CP_WAIT0()  asm volatile("cp.async.wait_group 0;" ::: "memory")

// ---------------------------------------------------------------------------
// K0: W [128][256] fp32 -> fp16 image [4 chunks][128 rows][64 k], SW128.
// ---------------------------------------------------------------------------
__global__ void whalf_kernel(const float* __restrict__ W) {
    int i = blockIdx.x * blockDim.x + threadIdx.x;   // 0..8191 float4s
    int row   = i >> 6;
    int kf    = i & 63;
    int chunk = kf >> 4;
    int k4    = kf & 15;
    float4 wv = *reinterpret_cast<const float4*>(W + row * TWOK + chunk * 64 + k4 * 4);
    __half2 h0 = __floats2half2_rn(wv.x, wv.y);
    __half2 h1 = __floats2half2_rn(wv.z, wv.w);
    uint32_t off = chunk * 16384 + sw128((uint32_t)(row * 128 + k4 * 8));
    *reinterpret_cast<uint2*>(g_Wh_img + off) =
        make_uint2(*reinterpret_cast<uint32_t*>(&h0),
                   *reinterpret_cast<uint32_t*>(&h1));
}

// ---------------------------------------------------------------------------
// K1: zero neighbor scratch + build fp16 copy of x.
// ---------------------------------------------------------------------------
__global__ void prep_kernel(const float* __restrict__ x, int n4, int nc8) {
    int i = blockIdx.x * blockDim.x + threadIdx.x;
    if (i < n4)
        reinterpret_cast<float4*>(g_neighbor)[i] = make_float4(0.f, 0.f, 0.f, 0.f);
    if (i < nc8) {
        float4 a = reinterpret_cast<const float4*>(x)[i * 2];
        float4 b = reinterpret_cast<const float4*>(x)[i * 2 + 1];
        __half2 h0 = __floats2half2_rn(a.x, a.y);
        __half2 h1 = __floats2half2_rn(a.z, a.w);
        __half2 h2 = __floats2half2_rn(b.x, b.y);
        __half2 h3 = __floats2half2_rn(b.z, b.w);
        uint4 o;
        o.x = *reinterpret_cast<uint32_t*>(&h0);
        o.y = *reinterpret_cast<uint32_t*>(&h1);
        o.z = *reinterpret_cast<uint32_t*>(&h2);
        o.w = *reinterpret_cast<uint32_t*>(&h3);
        reinterpret_cast<uint4*>(g_xh)[i] = o;
    }
}

// ---------------------------------------------------------------------------
// K3: neighbor fp32 -> fp16
// ---------------------------------------------------------------------------
__global__ void nconv_kernel(int nc8) {
    int i = blockIdx.x * blockDim.x + threadIdx.x;
    if (i < nc8) {
        float4 a = reinterpret_cast<const float4*>(g_neighbor)[i * 2];
        float4 b = reinterpret_cast<const float4*>(g_neighbor)[i * 2 + 1];
        __half2 h0 = __floats2half2_rn(a.x, a.y);
        __half2 h1 = __floats2half2_rn(a.z, a.w);
        __half2 h2 = __floats2half2_rn(b.x, b.y);
        __half2 h3 = __floats2half2_rn(b.z, b.w);
        uint4 o;
        o.x = *reinterpret_cast<uint32_t*>(&h0);
        o.y = *reinterpret_cast<uint32_t*>(&h1);
        o.z = *reinterpret_cast<uint32_t*>(&h2);
        o.w = *reinterpret_cast<uint32_t*>(&h3);
        reinterpret_cast<uint4*>(g_nh)[i] = o;
    }
}

// ---------------------------------------------------------------------------
// K2: SpMM (fp16 gather). Warp handles 32 edges coalesced + shfl broadcast.
// ---------------------------------------------------------------------------
__global__ void spmm_kernel(const int*   __restrict__ rows,
                            const int*   __restrict__ cols,
                            const float* __restrict__ vals,
                            int E) {
    int warp = (blockIdx.x * blockDim.x + threadIdx.x) >> 5;
    int lane = threadIdx.x & 31;
    long base = (long)warp * 32;
    if (base >= E) return;

    long e = base + lane;
    bool valid = e < E;
    long es = valid ? e : (long)E - 1;
    int   r = __ldg(rows + es);
    int   c = valid ? __ldg(cols + e) : 0;
    float v = valid ? __ldg(vals + e) : 0.f;

    const uint2* xh2 = reinterpret_cast<const uint2*>(g_xh);   // 4 halves
    float4*      nb4 = reinterpret_cast<float4*>(g_neighbor);

    int cur = __shfl_sync(0xffffffffu, r, 0);
    float4 acc = make_float4(0.f, 0.f, 0.f, 0.f);

    #pragma unroll
    for (int j = 0; j < 32; j++) {
        int   rj = __shfl_sync(0xffffffffu, r, j);
        int   cj = __shfl_sync(0xffffffffu, c, j);
        float vj = __shfl_sync(0xffffffffu, v, j);
        uint2 xv = xh2[(size_t)cj * 32 + lane];
        if (rj != cur) {                       // warp-uniform
            atomicAdd(&nb4[(size_t)cur * 32 + lane], acc);
            acc = make_float4(0.f, 0.f, 0.f, 0.f);
            cur = rj;
        }
        float2 f0 = __half22float2(*reinterpret_cast<__half2*>(&xv.x));
        float2 f1 = __half22float2(*reinterpret_cast<__half2*>(&xv.y));
        acc.x = fmaf(vj, f0.x, acc.x);
        acc.y = fmaf(vj, f0.y, acc.y);
        acc.z = fmaf(vj, f1.x, acc.z);
        acc.w = fmaf(vj, f1.y, acc.w);
    }
    atomicAdd(&nb4[(size_t)cur * 32 + lane], acc);
}

// ---------------------------------------------------------------------------
// K4: fp16 HMMA GEMM + bias + L2 normalize.
//   256 threads = 8 warps, 2 CTAs/SM. CTA tile 128x128, warp tile 64x32
//   (warp_m = wid&1, warp_n = wid>>1). K=256 in 4 chunks of 64.
//   W image (64KB) resident in smem; A double-buffered via cp.async (zfill).
// ---------------------------------------------------------------------------
#define SM_W    0
#define SM_A    65536                 // 2 stages x 16384
#define SM_BIAS (SM_A + 32768)        // 512
#define SM_RSS  (SM_BIAS + 512)       // float[4][128] = 2048
#define SM_TOTAL (SM_RSS + 2048)

__global__ void __launch_bounds__(256, 2)
gemm_norm_kernel(const float* __restrict__ b,
                 float* __restrict__ out,
                 int N) {
    extern __shared__ char smem[];
    uint32_t sb = smem_u32(smem);
    float* bias = reinterpret_cast<float*>(smem + SM_BIAS);
    float (*rss)[128] = reinterpret_cast<float (*)[128]>(smem + SM_RSS);

    int t    = threadIdx.x;
    int wid  = t >> 5;
    int lane = t & 31;
    int warp_m = wid & 1;          // rows warp_m*64 .. +63
    int warp_n = wid >> 1;         // cols warp_n*32 .. +31
    int rowBase = blockIdx.x * 128;

    // W image -> smem
    #pragma unroll
    for (int j = 0; j < 16; j++)
        CP_ASYNC16(sb + SM_W + t * 16 + j * 4096, g_Wh_img + t * 16 + j * 4096);

    // A stage: thread covers 4 x 16B units: i = t + 256j, r = i>>3, u8 = i&7
    const char* xb = reinterpret_cast<const char*>(g_xh);
    const char* nb = reinterpret_cast<const char*>(g_nh);

    auto stageA = [&](int c) {
        const char* srcb = (c < 2) ? (xb + (c) * 128) : (nb + (c - 2) * 128);
        uint32_t dstb = sb + SM_A + (c & 1) * 16384;
        #pragma unroll
        for (int j = 0; j < 4; j++) {
            int i  = t + 256 * j;
            int r  = i >> 3;
            int u8 = i & 7;
            int gr = rowBase + r;
            uint32_t sz = (gr < N) ? 16u : 0u;
            CP_ASYNC16Z(dstb + sw128((uint32_t)(r * 128 + u8 * 16)),
                        srcb + (size_t)gr * 256 + u8 * 16, sz);
        }
    };

    stageA(0); CP_COMMIT();          // group0 = W + A0
    stageA(1); CP_COMMIT();          // group1 = A1

    if (t < OUTF) bias[t] = __ldg(b + t);

    float acc[4][4][4];
    #pragma unroll
    for (int mi = 0; mi < 4; mi++)
        #pragma unroll
        for (int ni = 0; ni < 4; ni++)
            #pragma unroll
            for (int r = 0; r < 4; r++) acc[mi][ni][r] = 0.f;

    int aRow  = warp_m * 64 + (lane & 15);
    int aK8   = (lane >> 4) * 8;
    int bRowX = warp_n * 32 + (lane & 7) + ((lane >> 4) & 1) * 8;
    int bK8   = ((lane >> 3) & 1) * 8;

    #pragma unroll
    for (int c = 0; c < 4; c++) {
        if (c < 3) { CP_WAIT1(); } else { CP_WAIT0(); }
        __syncthreads();

        uint32_t aBuf  = sb + SM_A + (c & 1) * 16384;
        uint32_t wBase = sb + SM_W + c * 16384;
        #pragma unroll
        for (int kk = 0; kk < 64; kk += 16) {
            uint32_t a[4][4], bb[4][2];
            #pragma unroll
            for (int mi = 0; mi < 4; mi++) {
                uint32_t off = sw128((uint32_t)((aRow + mi * 16) * 128
                                                + (kk + aK8) * 2));
                ldsm_x4(a[mi][0], a[mi][1], a[mi][2], a[mi][3], aBuf + off);
            }
            #pragma unroll
            for (int p = 0; p < 2; p++) {
                uint32_t off = sw128((uint32_t)((bRowX + p * 16) * 128
                                                + (kk + bK8) * 2));
                ldsm_x4(bb[2*p][0], bb[2*p][1], bb[2*p+1][0], bb[2*p+1][1],
                        wBase + off);
            }
            #pragma unroll
            for (int mi = 0; mi < 4; mi++)
                #pragma unroll
                for (int ni = 0; ni < 4; ni++)
                    mma_f16(acc[mi][ni], a[mi], bb[ni]);
        }

        if (c < 2) {
            __syncthreads();          // everyone done reading buf (c&1)
            stageA(c + 2); CP_COMMIT();
        }
    }

    // ---- epilogue: bias, row sum-of-squares, normalize, store ----
    int colBase = warp_n * 32 + 2 * (lane & 3);
    #pragma unroll
    for (int mi = 0; mi < 4; mi++)
        #pragma unroll
        for (int ni = 0; ni < 4; ni++) {
            float b0 = bias[colBase + ni * 8];
            float b1 = bias[colBase + ni * 8 + 1];
            acc[mi][ni][0] += b0;  acc[mi][ni][1] += b1;
            acc[mi][ni][2] += b0;  acc[mi][ni][3] += b1;
        }

    #pragma unroll
    for (int mi = 0; mi < 4; mi++) {
        #pragma unroll
        for (int half = 0; half < 2; half++) {
            float s = 0.f;
            #pragma unroll
            for (int ni = 0; ni < 4; ni++) {
                float c0 = acc[mi][ni][half * 2 + 0];
                float c1 = acc[mi][ni][half * 2 + 1];
                s = fmaf(c0, c0, s);
                s = fmaf(c1, c1, s);
            }
            s += __shfl_xor_sync(0xffffffffu, s, 1);
            s += __shfl_xor_sync(0xffffffffu, s, 2);
            if ((lane & 3) == 0)
                rss[warp_n][warp_m * 64 + mi * 16 + half * 8 + (lane >> 2)] = s;
        }
    }
    __syncthreads();

    float2* out2 = reinterpret_cast<float2*>(out);
    #pragma unroll
    for (int mi = 0; mi < 4; mi++) {
        #pragma unroll
        for (int half = 0; half < 2; half++) {
            int rl  = warp_m * 64 + mi * 16 + half * 8 + (lane >> 2);
            int row = rowBase + rl;
            if (row < N) {
                float ss = rss[0][rl] + rss[1][rl] + rss[2][rl] + rss[3][rl];
                float scale = 1.f / fmaxf(sqrtf(ss), 1e-12f);
                #pragma unroll
                for (int ni = 0; ni < 4; ni++) {
                    float2 o;
                    o.x = acc[mi][ni][half * 2 + 0] * scale;
                    o.y = acc[mi][ni][half * 2 + 1] * scale;
                    out2[(size_t)row * 64 + (colBase + ni * 8) / 2] = o;
                }
            }
        }
    }
}

// ---------------------------------------------------------------------------
// Launch
// ---------------------------------------------------------------------------
extern "C" void kernel_launch(void* const* d_in, const int* in_sizes, int n_in,
                              void* d_out, int out_size) {
    const float* x    = (const float*)d_in[0];
    const int*   rows = (const int*)  d_in[1];
    const int*   cols = (const int*)  d_in[2];
    const float* vals = (const float*)d_in[3];
    const float* W    = (const float*)d_in[4];
    const float* b    = (const float*)d_in[5];
    float*       out  = (float*)d_out;

    int N = in_sizes[0] / INF;
    int E = in_sizes[1];

    cudaFuncSetAttribute(gemm_norm_kernel,
                         cudaFuncAttributeMaxDynamicSharedMemorySize, SM_TOTAL);

    // K0: W fp16 image
    whalf_kernel<<<32, 256>>>(W);

    // K1: zero neighbor + fp16 copy of x
    int n4  = N * (INF / 4);
    int nc8 = N * (INF / 8);
    prep_kernel<<<(n4 + 255) / 256, 256>>>(x, n4, nc8);

    // K2: SpMM
    int warps  = (E + 31) / 32;
    int blocks = (warps * 32 + 255) / 256;
    spmm_kernel<<<blocks, 256>>>(rows, cols, vals, E);

    // K3: neighbor -> fp16
    nconv_kernel<<<(nc8 + 255) / 256, 256>>>(nc8);

    // K4: fp16 HMMA GEMM + bias + normalize
    gemm_norm_kernel<<<(N + 127) / 128, 256, SM_TOTAL>>>(b, out, N);
}